// round 1
// baseline (speedup 1.0000x reference)
#include <cuda_runtime.h>

#define B_ 8
#define C_ 512
#define HW_ 4096
#define PER_IMG (C_*HW_)        // 2,097,152
#define TOT (B_*PER_IMG)        // 16,777,216

// Scratch (allocation-free rule: __device__ globals)
__device__ float g_f[2u*TOT];       // conv outputs / V, both branches: 134 MB
__device__ float g_S[2u*TOT];       // pre-softmax logits, both branches: 134 MB
__device__ float g_Msum[B_*HW_];    // m_opt + m_sar per (b,i,j)
__device__ float g_C2[B_*HW_];      // (z_opt*z_sar)^-2 per (b,i,j)

typedef unsigned long long u64;

// Packed fp32x2 FMA — the only way to reach 128 FMA/cyc/SM on sm_103a
// (FFMA 3-reg is half-rate; ptxas never emits FFMA2 from C++).
__device__ __forceinline__ u64 ffma2(u64 a, u64 b, u64 c) {
    u64 d;
    asm("fma.rn.f32x2 %0, %1, %2, %3;" : "=l"(d) : "l"(a), "l"(b), "l"(c));
    return d;
}
__device__ __forceinline__ u64 pack_dup(float x) {
    u64 r; unsigned xi = __float_as_uint(x);
    asm("mov.b64 %0, {%1, %1};" : "=l"(r) : "r"(xi));
    return r;
}

// ---------------------------------------------------------------------------
// Kernel A: f[o, n] = sum_c W[o,c] * X[c, n]   (M=512, N=4096, K=512)
// per (branch, batch). 128x128 block tile, BK=8, 8x8 per thread via f32x2.
// ---------------------------------------------------------------------------
__global__ __launch_bounds__(256, 2) void conv_gemm(
    const float* __restrict__ opt, const float* __restrict__ sar,
    const float* __restrict__ Wo,  const float* __restrict__ Ws)
{
    __shared__ float As[8][128];   // W tile, transposed: As[k][m]
    __shared__ float Bs[8][128];   // X tile: Bs[k][n]

    const int zz = blockIdx.z;            // 0..15 = branch*8 + batch
    const int br = zz >> 3, b = zz & 7;
    const float* X  = (br ? sar : opt) + (size_t)b * PER_IMG;
    const float* Wm = br ? Ws : Wo;
    float* F = g_f + (size_t)zz * PER_IMG;

    const int tid   = threadIdx.x;
    const int mBase = blockIdx.y << 7;
    const int nBase = blockIdx.x << 7;
    const int aRow  = tid >> 1, aCol = (tid & 1) << 2;   // 128x8 A tile
    const int bRow  = tid >> 5, bCol = (tid & 31) << 2;  // 8x128 B tile
    const int tx    = tid & 15, ty = tid >> 4;

    u64 acc[8][4];
    #pragma unroll
    for (int i = 0; i < 8; i++)
        #pragma unroll
        for (int j = 0; j < 4; j++) acc[i][j] = 0ull;

    const float* aPtr = Wm + (size_t)(mBase + aRow) * C_ + aCol;
    const float* bPtr = X + (size_t)bRow * HW_ + nBase + bCol;

    for (int k0 = 0; k0 < C_; k0 += 8) {
        float4 av = *(const float4*)(aPtr + k0);
        As[aCol + 0][aRow] = av.x;
        As[aCol + 1][aRow] = av.y;
        As[aCol + 2][aRow] = av.z;
        As[aCol + 3][aRow] = av.w;
        *(float4*)&Bs[bRow][bCol] = *(const float4*)(bPtr + (size_t)k0 * HW_);
        __syncthreads();

        #pragma unroll
        for (int kk = 0; kk < 8; kk++) {
            float4 a0 = *(const float4*)&As[kk][ty << 3];
            float4 a1 = *(const float4*)&As[kk][(ty << 3) + 4];
            const u64* b64 = (const u64*)&Bs[kk][tx << 3];
            u64 b2[4] = { b64[0], b64[1], b64[2], b64[3] };
            float ar[8] = { a0.x, a0.y, a0.z, a0.w, a1.x, a1.y, a1.z, a1.w };
            #pragma unroll
            for (int i = 0; i < 8; i++) {
                u64 ad = pack_dup(ar[i]);
                #pragma unroll
                for (int j = 0; j < 4; j++)
                    acc[i][j] = ffma2(ad, b2[j], acc[i][j]);
            }
        }
        __syncthreads();
    }

    #pragma unroll
    for (int i = 0; i < 8; i++) {
        u64* dst = (u64*)(F + (size_t)(mBase + (ty << 3) + i) * HW_ + nBase + (tx << 3));
        dst[0] = acc[i][0]; dst[1] = acc[i][1]; dst[2] = acc[i][2]; dst[3] = acc[i][3];
    }
}

// ---------------------------------------------------------------------------
// Kernel B: S_bc = A^T A, A = f[b,c] (64x64). One block per (br,b,c).
// ---------------------------------------------------------------------------
__global__ __launch_bounds__(256) void syrk_kernel()
{
    __shared__ float As[64][68];   // padded for conflict-free float4 rows

    const int c = blockIdx.x, b = blockIdx.y, br = blockIdx.z;
    const size_t base = (size_t)(br * B_ + b) * PER_IMG + (size_t)c * HW_;
    const float* A = g_f + base;
    const int tid = threadIdx.x;

    for (int idx = tid * 4; idx < 4096; idx += 1024) {
        float4 v = *(const float4*)(A + idx);
        *(float4*)&As[idx >> 6][idx & 63] = v;
    }
    __syncthreads();

    const int tx = tid & 15, ty = tid >> 4;
    const int i0 = ty << 2, j0 = tx << 2;
    u64 acc[4][2] = {};

    #pragma unroll 8
    for (int h = 0; h < 64; h++) {
        float4 a = *(const float4*)&As[h][i0];
        const u64* bp = (const u64*)&As[h][j0];
        u64 b0 = bp[0], b1 = bp[1];
        float ar[4] = { a.x, a.y, a.z, a.w };
        #pragma unroll
        for (int ii = 0; ii < 4; ii++) {
            u64 ad = pack_dup(ar[ii]);
            acc[ii][0] = ffma2(ad, b0, acc[ii][0]);
            acc[ii][1] = ffma2(ad, b1, acc[ii][1]);
        }
    }

    float* S = g_S + base;
    #pragma unroll
    for (int ii = 0; ii < 4; ii++) {
        u64* dst = (u64*)(S + (size_t)(i0 + ii) * 64 + j0);
        dst[0] = acc[ii][0]; dst[1] = acc[ii][1];
    }
}

// ---------------------------------------------------------------------------
// Kernel C: per-(b,i,j) online softmax stats over the channel axis (stride
// 4096) for both branches; store combined Msum = m1+m2 and (z1*z2)^-2.
// Block = (i, b), 256 threads: j = tid&63, channel-slice = tid>>6.
// ---------------------------------------------------------------------------
__global__ __launch_bounds__(256) void softmax_stats()
{
    const int i = blockIdx.x, b = blockIdx.y;
    const int tid = threadIdx.x;
    const int j = tid & 63, slice = tid >> 6;

    __shared__ float red_m[4][64], red_z[4][64];
    __shared__ float res_m[2][64], res_z[2][64];

    for (int br = 0; br < 2; br++) {
        const float* S = g_S + (size_t)(br * B_ + b) * PER_IMG + i * 64 + j;
        float m = -1e30f, z = 0.f;
        for (int cc = slice; cc < C_; cc += 4) {
            float v = S[(size_t)cc * HW_];
            if (v > m) { z = z * __expf(m - v) + 1.f; m = v; }
            else       { z += __expf(v - m); }
        }
        red_m[slice][j] = m; red_z[slice][j] = z;
        __syncthreads();
        if (slice == 0) {
            #pragma unroll
            for (int s = 1; s < 4; s++) {
                float m2 = red_m[s][j], z2 = red_z[s][j];
                float M = fmaxf(m, m2);
                z = z * __expf(m - M) + z2 * __expf(m2 - M);
                m = M;
            }
            res_m[br][j] = m; res_z[br][j] = z;
        }
        __syncthreads();
    }

    if (tid < 64) {
        float msum = res_m[0][j] + res_m[1][j];
        float rz = 1.f / (res_z[0][j] * res_z[1][j]);
        g_Msum[b * HW_ + i * 64 + j] = msum;
        g_C2[b * HW_ + i * 64 + j] = rz * rz;
    }
}

// ---------------------------------------------------------------------------
// Kernel D: Att = f1*f2*(P1*P2)^2 = f1*f2*exp(2*(s1+s2-Msum))*(z1*z2)^-2.
// One exp, no division, per element. float4 vectorized.
// ---------------------------------------------------------------------------
__global__ __launch_bounds__(256) void final_kernel(float* __restrict__ out)
{
    const int g = blockIdx.x * 256 + threadIdx.x;       // float4 index
    const size_t e = (size_t)g << 2;
    const int b = (int)(e / PER_IMG);
    const int s = (int)(e & (HW_ - 1));                 // (i,j) index

    const float4 f1 = *(const float4*)(g_f + e);
    const float4 f2 = *(const float4*)(g_f + (size_t)TOT + e);
    const float4 s1 = *(const float4*)(g_S + e);
    const float4 s2 = *(const float4*)(g_S + (size_t)TOT + e);
    const float4 ms = *(const float4*)(g_Msum + b * HW_ + s);
    const float4 c2 = *(const float4*)(g_C2 + b * HW_ + s);

    float4 o;
    o.x = f1.x * f2.x * __expf(2.f * (s1.x + s2.x - ms.x)) * c2.x;
    o.y = f1.y * f2.y * __expf(2.f * (s1.y + s2.y - ms.y)) * c2.y;
    o.z = f1.z * f2.z * __expf(2.f * (s1.z + s2.z - ms.z)) * c2.z;
    o.w = f1.w * f2.w * __expf(2.f * (s1.w + s2.w - ms.w)) * c2.w;
    *(float4*)(out + e) = o;
}

// ---------------------------------------------------------------------------
extern "C" void kernel_launch(void* const* d_in, const int* in_sizes, int n_in,
                              void* d_out, int out_size)
{
    // Inputs per metadata order: opt, sar, W_opt, W_sar. Identify by size
    // defensively (opt/sar are 16.7M elems; weights 262144).
    const float* big[2]   = { nullptr, nullptr };
    const float* small[2] = { nullptr, nullptr };
    int nb = 0, ns = 0;
    for (int i = 0; i < n_in; i++) {
        if (in_sizes[i] >= TOT) { if (nb < 2) big[nb] = (const float*)d_in[i]; nb++; }
        else                    { if (ns < 2) small[ns] = (const float*)d_in[i]; ns++; }
    }

    conv_gemm     <<<dim3(32, 4, 16), 256>>>(big[0], big[1], small[0], small[1]);
    syrk_kernel   <<<dim3(512, 8, 2), 256>>>();
    softmax_stats <<<dim3(64, 8),     256>>>();
    final_kernel  <<<TOT / 4 / 256,   256>>>((float*)d_out);
}

// round 2
// speedup vs baseline: 1.0553x; 1.0553x over previous
#include <cuda_runtime.h>

#define B_ 8
#define C_ 512
#define HW_ 4096
#define PER_IMG (C_*HW_)        // 2,097,152
#define TOT (B_*PER_IMG)        // 16,777,216

// Scratch (allocation-free rule: __device__ globals)
__device__ float g_f[2u*TOT];       // conv outputs / V, both branches: 134 MB
__device__ float g_S[2u*TOT];       // pre-softmax logits, both branches: 134 MB
__device__ float g_Msum[B_*HW_];    // m_opt + m_sar per (b,i,j)
__device__ float g_C2[B_*HW_];      // (z_opt*z_sar)^-2 per (b,i,j)

typedef unsigned long long u64;

// Packed fp32x2 FMA — the only way to reach 128 FMA/cyc/SM on sm_103a
// (FFMA 3-reg is half-rate; ptxas never emits FFMA2 from C++).
__device__ __forceinline__ u64 ffma2(u64 a, u64 b, u64 c) {
    u64 d;
    asm("fma.rn.f32x2 %0, %1, %2, %3;" : "=l"(d) : "l"(a), "l"(b), "l"(c));
    return d;
}
__device__ __forceinline__ u64 pack_dup(float x) {
    u64 r; unsigned xi = __float_as_uint(x);
    asm("mov.b64 %0, {%1, %1};" : "=l"(r) : "r"(xi));
    return r;
}

// ---------------------------------------------------------------------------
// Kernel A: f[o, n] = sum_c W[o,c] * X[c, n]   (M=512, N=4096, K=512)
// per (branch, batch). 128x128 block tile, BK=8, 8x8 per thread via f32x2.
// Double-buffered smem: global loads for step k+1 issued before compute on
// step k; one __syncthreads per K-step. L2-resident B tiles (~250cyc) hide
// under the 256-cyc FFMA2 window.
// ---------------------------------------------------------------------------
__global__ __launch_bounds__(256, 2) void conv_gemm(
    const float* __restrict__ opt, const float* __restrict__ sar,
    const float* __restrict__ Wo,  const float* __restrict__ Ws)
{
    __shared__ float As[2][8][128];   // W tile, transposed: As[buf][k][m]
    __shared__ float Bs[2][8][128];   // X tile: Bs[buf][k][n]

    const int zz = blockIdx.z;            // 0..15 = branch*8 + batch
    const int br = zz >> 3, b = zz & 7;
    const float* X  = (br ? sar : opt) + (size_t)b * PER_IMG;
    const float* Wm = br ? Ws : Wo;
    float* F = g_f + (size_t)zz * PER_IMG;

    const int tid   = threadIdx.x;
    const int mBase = blockIdx.y << 7;
    const int nBase = blockIdx.x << 7;
    const int aRow  = tid >> 1, aCol = (tid & 1) << 2;   // 128x8 A tile
    const int bRow  = tid >> 5, bCol = (tid & 31) << 2;  // 8x128 B tile
    const int tx    = tid & 15, ty = tid >> 4;

    u64 acc[8][4];
    #pragma unroll
    for (int i = 0; i < 8; i++)
        #pragma unroll
        for (int j = 0; j < 4; j++) acc[i][j] = 0ull;

    const float* aPtr = Wm + (size_t)(mBase + aRow) * C_ + aCol;
    const float* bPtr = X + (size_t)bRow * HW_ + nBase + bCol;

    // Prologue: tile 0 into buffer 0
    float4 av = *(const float4*)(aPtr);
    float4 bv = *(const float4*)(bPtr);
    As[0][aCol + 0][aRow] = av.x;
    As[0][aCol + 1][aRow] = av.y;
    As[0][aCol + 2][aRow] = av.z;
    As[0][aCol + 3][aRow] = av.w;
    *(float4*)&Bs[0][bRow][bCol] = bv;
    __syncthreads();

    int buf = 0;
    for (int k0 = 0; k0 < C_; k0 += 8) {
        const bool more = (k0 + 8) < C_;
        if (more) {
            av = *(const float4*)(aPtr + k0 + 8);
            bv = *(const float4*)(bPtr + (size_t)(k0 + 8) * HW_);
        }

        #pragma unroll
        for (int kk = 0; kk < 8; kk++) {
            float4 a0 = *(const float4*)&As[buf][kk][ty << 3];
            float4 a1 = *(const float4*)&As[buf][kk][(ty << 3) + 4];
            const u64* b64 = (const u64*)&Bs[buf][kk][tx << 3];
            u64 b2[4] = { b64[0], b64[1], b64[2], b64[3] };
            float ar[8] = { a0.x, a0.y, a0.z, a0.w, a1.x, a1.y, a1.z, a1.w };
            #pragma unroll
            for (int i = 0; i < 8; i++) {
                u64 ad = pack_dup(ar[i]);
                #pragma unroll
                for (int j = 0; j < 4; j++)
                    acc[i][j] = ffma2(ad, b2[j], acc[i][j]);
            }
        }

        if (more) {
            const int nb = buf ^ 1;
            As[nb][aCol + 0][aRow] = av.x;
            As[nb][aCol + 1][aRow] = av.y;
            As[nb][aCol + 2][aRow] = av.z;
            As[nb][aCol + 3][aRow] = av.w;
            *(float4*)&Bs[nb][bRow][bCol] = bv;
        }
        __syncthreads();
        buf ^= 1;
    }

    #pragma unroll
    for (int i = 0; i < 8; i++) {
        u64* dst = (u64*)(F + (size_t)(mBase + (ty << 3) + i) * HW_ + nBase + (tx << 3));
        dst[0] = acc[i][0]; dst[1] = acc[i][1]; dst[2] = acc[i][2]; dst[3] = acc[i][3];
    }
}

// ---------------------------------------------------------------------------
// Kernel B: S_bc = A^T A, A = f[b,c] (64x64). One block per (br,b,c).
// ---------------------------------------------------------------------------
__global__ __launch_bounds__(256) void syrk_kernel()
{
    __shared__ float As[64][68];   // padded for conflict-free float4 rows

    const int c = blockIdx.x, b = blockIdx.y, br = blockIdx.z;
    const size_t base = (size_t)(br * B_ + b) * PER_IMG + (size_t)c * HW_;
    const float* A = g_f + base;
    const int tid = threadIdx.x;

    for (int idx = tid * 4; idx < 4096; idx += 1024) {
        float4 v = *(const float4*)(A + idx);
        *(float4*)&As[idx >> 6][idx & 63] = v;
    }
    __syncthreads();

    const int tx = tid & 15, ty = tid >> 4;
    const int i0 = ty << 2, j0 = tx << 2;
    u64 acc[4][2] = {};

    #pragma unroll 8
    for (int h = 0; h < 64; h++) {
        float4 a = *(const float4*)&As[h][i0];
        const u64* bp = (const u64*)&As[h][j0];
        u64 b0 = bp[0], b1 = bp[1];
        float ar[4] = { a.x, a.y, a.z, a.w };
        #pragma unroll
        for (int ii = 0; ii < 4; ii++) {
            u64 ad = pack_dup(ar[ii]);
            acc[ii][0] = ffma2(ad, b0, acc[ii][0]);
            acc[ii][1] = ffma2(ad, b1, acc[ii][1]);
        }
    }

    float* S = g_S + base;
    #pragma unroll
    for (int ii = 0; ii < 4; ii++) {
        u64* dst = (u64*)(S + (size_t)(i0 + ii) * 64 + j0);
        dst[0] = acc[ii][0]; dst[1] = acc[ii][1];
    }
}

// ---------------------------------------------------------------------------
// Kernel C: per-(b,i,j) online softmax stats over the channel axis (stride
// 4096) for both branches; store combined Msum = m1+m2 and (z1*z2)^-2.
// Block = (i, b), 256 threads: j = tid&63, channel-slice = tid>>6.
// ---------------------------------------------------------------------------
__global__ __launch_bounds__(256) void softmax_stats()
{
    const int i = blockIdx.x, b = blockIdx.y;
    const int tid = threadIdx.x;
    const int j = tid & 63, slice = tid >> 6;

    __shared__ float red_m[4][64], red_z[4][64];
    __shared__ float res_m[2][64], res_z[2][64];

    for (int br = 0; br < 2; br++) {
        const float* S = g_S + (size_t)(br * B_ + b) * PER_IMG + i * 64 + j;
        float m = -1e30f, z = 0.f;
        for (int cc = slice; cc < C_; cc += 4) {
            float v = S[(size_t)cc * HW_];
            if (v > m) { z = z * __expf(m - v) + 1.f; m = v; }
            else       { z += __expf(v - m); }
        }
        red_m[slice][j] = m; red_z[slice][j] = z;
        __syncthreads();
        if (slice == 0) {
            #pragma unroll
            for (int s = 1; s < 4; s++) {
                float m2 = red_m[s][j], z2 = red_z[s][j];
                float M = fmaxf(m, m2);
                z = z * __expf(m - M) + z2 * __expf(m2 - M);
                m = M;
            }
            res_m[br][j] = m; res_z[br][j] = z;
        }
        __syncthreads();
    }

    if (tid < 64) {
        float msum = res_m[0][j] + res_m[1][j];
        float rz = 1.f / (res_z[0][j] * res_z[1][j]);
        g_Msum[b * HW_ + i * 64 + j] = msum;
        g_C2[b * HW_ + i * 64 + j] = rz * rz;
    }
}

// ---------------------------------------------------------------------------
// Kernel D: Att = f1*f2*(P1*P2)^2 = f1*f2*exp(2*(s1+s2-Msum))*(z1*z2)^-2.
// One exp, no division, per element. float4 vectorized. At DRAM roofline.
// ---------------------------------------------------------------------------
__global__ __launch_bounds__(256) void final_kernel(float* __restrict__ out)
{
    const int g = blockIdx.x * 256 + threadIdx.x;       // float4 index
    const size_t e = (size_t)g << 2;
    const int b = (int)(e / PER_IMG);
    const int s = (int)(e & (HW_ - 1));                 // (i,j) index

    const float4 f1 = *(const float4*)(g_f + e);
    const float4 f2 = *(const float4*)(g_f + (size_t)TOT + e);
    const float4 s1 = *(const float4*)(g_S + e);
    const float4 s2 = *(const float4*)(g_S + (size_t)TOT + e);
    const float4 ms = *(const float4*)(g_Msum + b * HW_ + s);
    const float4 c2 = *(const float4*)(g_C2 + b * HW_ + s);

    float4 o;
    o.x = f1.x * f2.x * __expf(2.f * (s1.x + s2.x - ms.x)) * c2.x;
    o.y = f1.y * f2.y * __expf(2.f * (s1.y + s2.y - ms.y)) * c2.y;
    o.z = f1.z * f2.z * __expf(2.f * (s1.z + s2.z - ms.z)) * c2.z;
    o.w = f1.w * f2.w * __expf(2.f * (s1.w + s2.w - ms.w)) * c2.w;
    *(float4*)(out + e) = o;
}

// ---------------------------------------------------------------------------
extern "C" void kernel_launch(void* const* d_in, const int* in_sizes, int n_in,
                              void* d_out, int out_size)
{
    // Inputs per metadata order: opt, sar, W_opt, W_sar. Identify by size
    // defensively (opt/sar are 16.7M elems; weights 262144).
    const float* big[2]   = { nullptr, nullptr };
    const float* small[2] = { nullptr, nullptr };
    int nb = 0, ns = 0;
    for (int i = 0; i < n_in; i++) {
        if (in_sizes[i] >= TOT) { if (nb < 2) big[nb] = (const float*)d_in[i]; nb++; }
        else                    { if (ns < 2) small[ns] = (const float*)d_in[i]; ns++; }
    }

    conv_gemm     <<<dim3(32, 4, 16), 256>>>(big[0], big[1], small[0], small[1]);
    syrk_kernel   <<<dim3(512, 8, 2), 256>>>();
    softmax_stats <<<dim3(64, 8),     256>>>();
    final_kernel  <<<TOT / 4 / 256,   256>>>((float*)d_out);
}